// round 1
// baseline (speedup 1.0000x reference)
#include <cuda_runtime.h>
#include <cuda_bf16.h>

#define DIM 64

__global__ void svdpp_kernel(const int* __restrict__ user_ids,
                             const int* __restrict__ item_ids,
                             const int* __restrict__ offsets,
                             const int* __restrict__ flat_implicit,
                             const float* __restrict__ user_emb,
                             const float* __restrict__ item_emb,
                             const float* __restrict__ imp_emb,
                             const float* __restrict__ user_bias,
                             const float* __restrict__ item_bias,
                             const float* __restrict__ global_bias,
                             float* __restrict__ out,
                             int B, int N) {
    const int b = blockIdx.x;
    const int d = threadIdx.x;          // 0..63, one dim per thread

    const int start = offsets[b];
    const int end   = (b + 1 < B) ? offsets[b + 1] : N;
    const int len   = end - start;

    float acc = 0.0f;
    int j = start;
    // Unrolled x4 for memory-level parallelism (loads into L2-resident table)
    for (; j + 4 <= end; j += 4) {
        const int i0 = flat_implicit[j + 0];
        const int i1 = flat_implicit[j + 1];
        const int i2 = flat_implicit[j + 2];
        const int i3 = flat_implicit[j + 3];
        float a0 = imp_emb[(size_t)i0 * DIM + d];
        float a1 = imp_emb[(size_t)i1 * DIM + d];
        float a2 = imp_emb[(size_t)i2 * DIM + d];
        float a3 = imp_emb[(size_t)i3 * DIM + d];
        acc += a0 + a1 + a2 + a3;
    }
    for (; j < end; ++j) {
        acc += imp_emb[(size_t)flat_implicit[j] * DIM + d];
    }

    const float invnorm = (len > 0) ? rsqrtf((float)len) : 1.0f;

    const int u  = user_ids[b];
    const int it = item_ids[b];

    const float fu  = user_emb[(size_t)u * DIM + d] + acc * invnorm;
    float val       = fu * item_emb[(size_t)it * DIM + d];

    // Reduce 64 values (2 warps): warp shuffle then shared combine
    #pragma unroll
    for (int off = 16; off > 0; off >>= 1)
        val += __shfl_down_sync(0xffffffffu, val, off);

    __shared__ float s[2];
    if ((threadIdx.x & 31) == 0) s[threadIdx.x >> 5] = val;
    __syncthreads();

    if (threadIdx.x == 0) {
        const float dot = s[0] + s[1];
        out[b] = dot + user_bias[u] + item_bias[it] + global_bias[0];
    }
}

extern "C" void kernel_launch(void* const* d_in, const int* in_sizes, int n_in,
                              void* d_out, int out_size) {
    const int*   user_ids      = (const int*)d_in[0];
    const int*   item_ids      = (const int*)d_in[1];
    const int*   offsets       = (const int*)d_in[2];
    const int*   flat_implicit = (const int*)d_in[3];
    const float* user_emb      = (const float*)d_in[4];
    const float* item_emb      = (const float*)d_in[5];
    const float* imp_emb       = (const float*)d_in[6];
    const float* user_bias     = (const float*)d_in[7];
    const float* item_bias     = (const float*)d_in[8];
    const float* global_bias   = (const float*)d_in[9];
    float*       out           = (float*)d_out;

    const int B = in_sizes[0];          // 16384
    const int N = in_sizes[3];          // 819200

    svdpp_kernel<<<B, DIM>>>(user_ids, item_ids, offsets, flat_implicit,
                             user_emb, item_emb, imp_emb,
                             user_bias, item_bias, global_bias,
                             out, B, N);
}

// round 2
// speedup vs baseline: 1.9421x; 1.9421x over previous
#include <cuda_runtime.h>
#include <cuda_bf16.h>

#define DIM 64
// 64 threads: 4 item-slots x 16 lanes; each lane owns 4 dims via float4.

__global__ void svdpp_kernel(const int* __restrict__ user_ids,
                             const int* __restrict__ item_ids,
                             const int* __restrict__ offsets,
                             const int* __restrict__ flat_implicit,
                             const float4* __restrict__ user_emb4,
                             const float4* __restrict__ item_emb4,
                             const float4* __restrict__ imp_emb4,
                             const float* __restrict__ user_bias,
                             const float* __restrict__ item_bias,
                             const float* __restrict__ global_bias,
                             float* __restrict__ out,
                             int B, int N) {
    const int b    = blockIdx.x;
    const int tid  = threadIdx.x;
    const int lane = tid & 15;          // which float4 of the row (16 x 16B = 256B row)
    const int slot = tid >> 4;          // item slot 0..3

    const int start = offsets[b];
    const int end   = (b + 1 < B) ? offsets[b + 1] : N;
    const int len   = end - start;

    float4 acc = make_float4(0.f, 0.f, 0.f, 0.f);

    int j = start + slot;
    // Unrolled x2: each thread keeps two LDG.128 in flight.
    for (; j + 4 < end; j += 8) {
        const int i0 = flat_implicit[j];
        const int i1 = flat_implicit[j + 4];
        const float4 a = __ldg(&imp_emb4[(size_t)i0 * 16 + lane]);
        const float4 c = __ldg(&imp_emb4[(size_t)i1 * 16 + lane]);
        acc.x += a.x + c.x;
        acc.y += a.y + c.y;
        acc.z += a.z + c.z;
        acc.w += a.w + c.w;
    }
    if (j < end) {
        const float4 a = __ldg(&imp_emb4[(size_t)flat_implicit[j] * 16 + lane]);
        acc.x += a.x; acc.y += a.y; acc.z += a.z; acc.w += a.w;
    }

    // Reduce across 4 slots. Slots 0,1 are in warp 0; slots 2,3 in warp 1.
    acc.x += __shfl_xor_sync(0xffffffffu, acc.x, 16);
    acc.y += __shfl_xor_sync(0xffffffffu, acc.y, 16);
    acc.z += __shfl_xor_sync(0xffffffffu, acc.z, 16);
    acc.w += __shfl_xor_sync(0xffffffffu, acc.w, 16);

    __shared__ float4 s[16];
    if (tid >= 32 && tid < 48) s[lane] = acc;   // warp 1, lanes 0-15
    __syncthreads();

    if (tid < 16) {
        const float4 o = s[tid];
        acc.x += o.x; acc.y += o.y; acc.z += o.z; acc.w += o.w;

        const float invnorm = (len > 0) ? rsqrtf((float)len) : 1.0f;
        const int u  = user_ids[b];
        const int it = item_ids[b];

        const float4 u4 = __ldg(&user_emb4[(size_t)u * 16 + tid]);
        const float4 i4 = __ldg(&item_emb4[(size_t)it * 16 + tid]);

        float dot = (u4.x + acc.x * invnorm) * i4.x
                  + (u4.y + acc.y * invnorm) * i4.y
                  + (u4.z + acc.z * invnorm) * i4.z
                  + (u4.w + acc.w * invnorm) * i4.w;

        // Reduce 16 lanes within warp 0
        #pragma unroll
        for (int off = 8; off > 0; off >>= 1)
            dot += __shfl_down_sync(0x0000ffffu, dot, off);

        if (tid == 0)
            out[b] = dot + user_bias[u] + item_bias[it] + global_bias[0];
    }
}

extern "C" void kernel_launch(void* const* d_in, const int* in_sizes, int n_in,
                              void* d_out, int out_size) {
    const int*    user_ids      = (const int*)d_in[0];
    const int*    item_ids      = (const int*)d_in[1];
    const int*    offsets       = (const int*)d_in[2];
    const int*    flat_implicit = (const int*)d_in[3];
    const float4* user_emb4     = (const float4*)d_in[4];
    const float4* item_emb4     = (const float4*)d_in[5];
    const float4* imp_emb4      = (const float4*)d_in[6];
    const float*  user_bias     = (const float*)d_in[7];
    const float*  item_bias     = (const float*)d_in[8];
    const float*  global_bias   = (const float*)d_in[9];
    float*        out           = (float*)d_out;

    const int B = in_sizes[0];          // 16384
    const int N = in_sizes[3];          // 819200

    svdpp_kernel<<<B, DIM>>>(user_ids, item_ids, offsets, flat_implicit,
                             user_emb4, item_emb4, imp_emb4,
                             user_bias, item_bias, global_bias,
                             out, B, N);
}